// round 1
// baseline (speedup 1.0000x reference)
#include <cuda_runtime.h>
#include <math.h>
#include <stdint.h>

// ---------------- problem constants ----------------
#define BQ    32
#define LIN   392
#define LQ    196
#define DM    512
#define DEPTHQ 4
#define DI    1024
#define DS    16
#define DTR   32
#define KC    4
#define MTOK  (BQ*LQ)      // 6272 tokens

// ---------------- scratch (static device memory; no allocation) ----------------
__device__ float g_x  [MTOK*DM];
__device__ float g_h  [MTOK*DM];
__device__ float g_t1 [MTOK*DM];
__device__ float g_t2 [MTOK*DM];
__device__ float g_xz [MTOK*2*DI];
__device__ float g_xi [MTOK*DI];
__device__ float g_dbc[MTOK*(DTR+2*DS)];
__device__ float g_dt [MTOK*DI];
__device__ float g_y  [MTOK*DI];

// ---------------- helpers ----------------
__device__ __forceinline__ unsigned long long pack2(float lo, float hi) {
    unsigned long long r;
    asm("mov.b64 %0, {%1,%2};" : "=l"(r) : "f"(lo), "f"(hi));
    return r;
}
__device__ __forceinline__ void unpack2(unsigned long long v, float& lo, float& hi) {
    asm("mov.b64 {%0,%1}, %2;" : "=f"(lo), "=f"(hi) : "l"(v));
}
__device__ __forceinline__ unsigned long long fma2(unsigned long long a,
                                                   unsigned long long b,
                                                   unsigned long long c) {
    unsigned long long d;
    asm("fma.rn.f32x2 %0, %1, %2, %3;" : "=l"(d) : "l"(a), "l"(b), "l"(c));
    return d;
}
__device__ __forceinline__ float fast_exp2(float x) {
    float r;
    asm("ex2.approx.f32 %0, %1;" : "=f"(r) : "f"(x));
    return r;
}
__device__ __forceinline__ float fast_sigmoid(float x) {
    return 1.0f / (1.0f + __expf(-x));
}

// ---------------- pooling ----------------
__global__ void __launch_bounds__(256) k_pool(const float* __restrict__ in, float* __restrict__ out) {
    int i = blockIdx.x * 256 + threadIdx.x;
    if (i >= MTOK*DM) return;
    int c = i % DM;
    int t = i / DM;
    int l = t % LQ;
    int b = t / LQ;
    const float* p = in + ((size_t)(b*LIN + 2*l) * DM + c);
    out[i] = fmaxf(p[0], p[DM]);
}

// ---------------- GEMM: C[M,N] = A[M,(lda)] (cols 0..K) * W[N,K]^T  (+epilogue) ----------------
// EPI: 0 = +bias(opt)   1 = +bias + embed[row/LQ]   2 = +extra[row,col] (residual)
//      3 = softplus(acc + bias)
template<int EPI>
__device__ __forceinline__ float epi_apply(float acc, int row, int col, int N,
                                           const float* __restrict__ bias,
                                           const float* __restrict__ extra) {
    if constexpr (EPI == 0) {
        return bias ? acc + bias[col] : acc;
    } else if constexpr (EPI == 1) {
        return acc + bias[col] + extra[(size_t)(row / LQ) * N + col];
    } else if constexpr (EPI == 2) {
        return acc + extra[(size_t)row * N + col];
    } else { // 3: softplus
        float v = acc + bias[col];
        return v > 20.0f ? v : log1pf(expf(v));
    }
}

template<int BM, int BN, int BK, int TM, int TN, int EPI>
__global__ void __launch_bounds__(256) k_gemm(
    const float* __restrict__ A, int lda,
    const float* __restrict__ W,
    const float* __restrict__ bias,
    const float* __restrict__ extra,
    float* __restrict__ C,
    int M, int N, int K)
{
    static_assert((BM/TM)*(BN/TN) == 256, "256 threads");
    static_assert(TM % 4 == 0 && TN % 2 == 0, "vector widths");
    __shared__ __align__(16) float As[BK][BM];
    __shared__ __align__(16) float Ws[BK][BN];

    const int tid = threadIdx.x;
    const int bm  = blockIdx.y * BM;
    const int bn  = blockIdx.x * BN;
    const int tn  = tid % (BN/TN);
    const int tm  = tid / (BN/TN);

    unsigned long long acc[TM][TN/2];
#pragma unroll
    for (int i = 0; i < TM; i++)
#pragma unroll
        for (int j = 0; j < TN/2; j++) acc[i][j] = 0ull;

    const int AT   = BK/4;          // threads per row for float4 loads (=2)
    const int arow = tid / AT;
    const int acol = (tid % AT) * 4;
    const int RPI  = 256 / AT;      // rows per iteration (=128)

    for (int k0 = 0; k0 < K; k0 += BK) {
#pragma unroll
        for (int r = arow; r < BM; r += RPI) {
            float4 v = *(const float4*)(A + (size_t)(bm + r) * lda + k0 + acol);
            As[acol+0][r] = v.x; As[acol+1][r] = v.y;
            As[acol+2][r] = v.z; As[acol+3][r] = v.w;
        }
#pragma unroll
        for (int r = arow; r < BN; r += RPI) {
            float4 v = *(const float4*)(W + (size_t)(bn + r) * K + k0 + acol);
            Ws[acol+0][r] = v.x; Ws[acol+1][r] = v.y;
            Ws[acol+2][r] = v.z; Ws[acol+3][r] = v.w;
        }
        __syncthreads();
#pragma unroll
        for (int k = 0; k < BK; k++) {
            float ar[TM];
#pragma unroll
            for (int i = 0; i < TM; i += 4) {
                float4 v = *(const float4*)(&As[k][tm*TM + i]);
                ar[i] = v.x; ar[i+1] = v.y; ar[i+2] = v.z; ar[i+3] = v.w;
            }
            unsigned long long w2[TN/2];
#pragma unroll
            for (int j = 0; j < TN/2; j++)
                w2[j] = *(const unsigned long long*)(&Ws[k][tn*TN + 2*j]);
#pragma unroll
            for (int i = 0; i < TM; i++) {
                unsigned long long a2 = pack2(ar[i], ar[i]);
#pragma unroll
                for (int j = 0; j < TN/2; j++)
                    acc[i][j] = fma2(a2, w2[j], acc[i][j]);
            }
        }
        __syncthreads();
    }

#pragma unroll
    for (int i = 0; i < TM; i++) {
        int row = bm + tm*TM + i;
#pragma unroll
        for (int j = 0; j < TN/2; j++) {
            float v0, v1;
            unpack2(acc[i][j], v0, v1);
            int col = bn + tn*TN + 2*j;
            C[(size_t)row * N + col    ] = epi_apply<EPI>(v0, row, col,     N, bias, extra);
            C[(size_t)row * N + col + 1] = epi_apply<EPI>(v1, row, col + 1, N, bias, extra);
        }
    }
}

// ---------------- layernorm (rows of 512) ----------------
__global__ void __launch_bounds__(256) k_ln(const float* __restrict__ x,
                                            const float* __restrict__ w,
                                            const float* __restrict__ b,
                                            float* __restrict__ out) {
    int row = blockIdx.x;
    int t = threadIdx.x;
    const float* px = x + (size_t)row * DM;
    float v0 = px[t], v1 = px[t + 256];
    float s = v0 + v1, ss = v0*v0 + v1*v1;
    __shared__ float sh[16];
#pragma unroll
    for (int o = 16; o; o >>= 1) {
        s  += __shfl_xor_sync(0xffffffffu, s,  o);
        ss += __shfl_xor_sync(0xffffffffu, ss, o);
    }
    if ((t & 31) == 0) { sh[t >> 5] = s; sh[8 + (t >> 5)] = ss; }
    __syncthreads();
    if (t < 32) {
        float a = (t < 8)  ? sh[t]     : 0.0f;
        float c = (t < 8)  ? sh[8 + t] : 0.0f;
#pragma unroll
        for (int o = 4; o; o >>= 1) {
            a += __shfl_xor_sync(0xffffffffu, a, o);
            c += __shfl_xor_sync(0xffffffffu, c, o);
        }
        if (t == 0) { sh[0] = a; sh[1] = c; }
    }
    __syncthreads();
    float mu  = sh[0] * (1.0f / DM);
    float var = sh[1] * (1.0f / DM) - mu * mu;
    float rs  = rsqrtf(var + 1e-5f);
    out[(size_t)row * DM + t      ] = (v0 - mu) * rs * w[t]       + b[t];
    out[(size_t)row * DM + t + 256] = (v1 - mu) * rs * w[t + 256] + b[t + 256];
}

// ---------------- rmsnorm + silu (rows of 512) ----------------
__global__ void __launch_bounds__(256) k_rmssilu(const float* __restrict__ x,
                                                 const float* __restrict__ w,
                                                 float* __restrict__ out) {
    int row = blockIdx.x;
    int t = threadIdx.x;
    const float* px = x + (size_t)row * DM;
    float v0 = px[t], v1 = px[t + 256];
    float ss = v0*v0 + v1*v1;
    __shared__ float sh[8];
#pragma unroll
    for (int o = 16; o; o >>= 1) ss += __shfl_xor_sync(0xffffffffu, ss, o);
    if ((t & 31) == 0) sh[t >> 5] = ss;
    __syncthreads();
    if (t < 32) {
        float a = (t < 8) ? sh[t] : 0.0f;
#pragma unroll
        for (int o = 4; o; o >>= 1) a += __shfl_xor_sync(0xffffffffu, a, o);
        if (t == 0) sh[0] = a;
    }
    __syncthreads();
    float rs = rsqrtf(sh[0] * (1.0f / DM) + 1e-5f);
    float a0 = v0 * rs * w[t];
    float a1 = v1 * rs * w[t + 256];
    out[(size_t)row * DM + t      ] = a0 * fast_sigmoid(a0);
    out[(size_t)row * DM + t + 256] = a1 * fast_sigmoid(a1);
}

// ---------------- causal depthwise conv (K=4) + bias + silu ----------------
__global__ void __launch_bounds__(256) k_conv(const float* __restrict__ xz,
                                              const float* __restrict__ cw,
                                              const float* __restrict__ cb,
                                              float* __restrict__ xi) {
    int i = blockIdx.x * 256 + threadIdx.x;
    if (i >= MTOK*DI) return;
    int d = i & (DI - 1);
    int t = i >> 10;
    int l = t % LQ;
    int b = t / LQ;
    const float* base = xz + (size_t)(b*LQ) * (2*DI) + d;  // stride 2*DI per l
    float acc = cb[d];
#pragma unroll
    for (int k = 0; k < KC; k++) {
        int ll = l - (KC - 1) + k;
        if (ll >= 0) acc = fmaf(cw[d*KC + k], base[(size_t)ll * (2*DI)], acc);
    }
    xi[i] = acc * fast_sigmoid(acc);
}

// ---------------- selective scan + gating epilogue ----------------
__global__ void __launch_bounds__(128) k_scan(
    const float* __restrict__ dt, const float* __restrict__ xi,
    const float* __restrict__ dbc, const float* __restrict__ xz,
    const float* __restrict__ A_log, const float* __restrict__ Dp,
    float* __restrict__ y)
{
    const int b = blockIdx.y;
    const int d = blockIdx.x * 128 + threadIdx.x;
    __shared__ float sB[LQ][DS];
    __shared__ float sC[LQ][DS];
    for (int idx = threadIdx.x; idx < LQ*2*DS; idx += 128) {
        int l = idx >> 5;
        int c = idx & 31;
        float v = dbc[(size_t)(b*LQ + l) * (DTR + 2*DS) + DTR + c];
        if (c < DS) sB[l][c] = v; else sC[l][c - DS] = v;
    }
    float Asc[DS];
#pragma unroll
    for (int n = 0; n < DS; n++)
        Asc[n] = -__expf(A_log[(size_t)d*DS + n]) * 1.4426950408889634f; // *log2(e)
    const float Dv = Dp[d];
    float st[DS];
#pragma unroll
    for (int n = 0; n < DS; n++) st[n] = 0.0f;
    __syncthreads();

    for (int l = 0; l < LQ; l++) {
        size_t off = (size_t)(b*LQ + l) * DI + d;
        float dtv = dt[off];
        float xiv = xi[off];
        float zv  = xz[(size_t)(b*LQ + l) * (2*DI) + DI + d];
        float u   = dtv * xiv;
        float acc = 0.0f;
#pragma unroll
        for (int n = 0; n < DS; n++) {
            float dA = fast_exp2(dtv * Asc[n]);
            st[n] = fmaf(dA, st[n], u * sB[l][n]);
            acc   = fmaf(st[n], sC[l][n], acc);
        }
        float yv = fmaf(Dv, xiv, acc);
        y[off] = yv * (zv * fast_sigmoid(zv));
    }
}

// ---------------- launch ----------------
extern "C" void kernel_launch(void* const* d_in, const int* in_sizes, int n_in,
                              void* d_out, int out_size) {
    (void)in_sizes; (void)n_in; (void)out_size;
    const float* motion   = (const float*)d_in[0];
    const float* embed    = (const float*)d_in[1];
    const float* mlp_w1   = (const float*)d_in[2];
    const float* mlp_b1   = (const float*)d_in[3];
    const float* mlp_rmsw = (const float*)d_in[4];
    const float* mlp_w2   = (const float*)d_in[5];
    const float* mlp_b2   = (const float*)d_in[6];
    const float* ln_w     = (const float*)d_in[7];
    const float* ln_b     = (const float*)d_in[8];
    const float* in_w     = (const float*)d_in[9];
    const float* conv_w   = (const float*)d_in[10];
    const float* conv_b   = (const float*)d_in[11];
    const float* xproj_w  = (const float*)d_in[12];
    const float* dt_w     = (const float*)d_in[13];
    const float* dt_b     = (const float*)d_in[14];
    const float* A_log    = (const float*)d_in[15];
    const float* D_param  = (const float*)d_in[16];
    const float* out_w    = (const float*)d_in[17];
    const float* lnf_w    = (const float*)d_in[18];
    const float* lnf_b    = (const float*)d_in[19];

    float *x, *h, *t1, *t2, *xz, *xi, *dbc, *dtb, *y;
    cudaGetSymbolAddress((void**)&x,   g_x);
    cudaGetSymbolAddress((void**)&h,   g_h);
    cudaGetSymbolAddress((void**)&t1,  g_t1);
    cudaGetSymbolAddress((void**)&t2,  g_t2);
    cudaGetSymbolAddress((void**)&xz,  g_xz);
    cudaGetSymbolAddress((void**)&xi,  g_xi);
    cudaGetSymbolAddress((void**)&dbc, g_dbc);
    cudaGetSymbolAddress((void**)&dtb, g_dt);
    cudaGetSymbolAddress((void**)&y,   g_y);

    // 1. max-pool pairs along L
    k_pool<<<(MTOK*DM + 255)/256, 256>>>(motion, h);

    // 2. mlp: t1 = pool @ w1^T + b1 ; t2 = silu(rmsnorm(t1)) ; x = t2 @ w2^T + b2 + embed
    k_gemm<128,128,8,8,8,0><<<dim3(DM/128, MTOK/128), 256>>>(h, DM, mlp_w1, mlp_b1, nullptr, t1, MTOK, DM, DM);
    k_rmssilu<<<MTOK, 256>>>(t1, mlp_rmsw, t2);
    k_gemm<128,128,8,8,8,1><<<dim3(DM/128, MTOK/128), 256>>>(t2, DM, mlp_w2, mlp_b2, embed, x, MTOK, DM, DM);

    // 3. mamba layers
    for (int i = 0; i < DEPTHQ; i++) {
        const float* lw   = ln_w    + (size_t)i * DM;
        const float* lb   = ln_b    + (size_t)i * DM;
        const float* iw   = in_w    + (size_t)i * 2*DI*DM;
        const float* cw   = conv_w  + (size_t)i * DI*KC;
        const float* cb   = conv_b  + (size_t)i * DI;
        const float* xpw  = xproj_w + (size_t)i * (DTR+2*DS)*DI;
        const float* dtw  = dt_w    + (size_t)i * DI*DTR;
        const float* dtbi = dt_b    + (size_t)i * DI;
        const float* al   = A_log   + (size_t)i * DI*DS;
        const float* dp   = D_param + (size_t)i * DI;
        const float* ow   = out_w   + (size_t)i * DM*DI;

        k_ln<<<MTOK, 256>>>(x, lw, lb, h);
        // xz = h @ in_w^T   (M=6272, N=2048, K=512)
        k_gemm<128,128,8,8,8,0><<<dim3(2*DI/128, MTOK/128), 256>>>(h, DM, iw, nullptr, nullptr, xz, MTOK, 2*DI, DM);
        // xi = silu(causal_conv(xz[:, :DI]) + cb)
        k_conv<<<(MTOK*DI + 255)/256, 256>>>(xz, cw, cb, xi);
        // dbc = xi @ xproj^T  (N=64, K=1024)
        k_gemm<64,64,8,4,4,0><<<dim3(1, MTOK/64), 256>>>(xi, DI, xpw, nullptr, nullptr, dbc, MTOK, DTR+2*DS, DI);
        // dt = softplus(dbc[:, :32] @ dt_w^T + dt_b)   (N=1024, K=32, lda=64)
        k_gemm<128,128,8,8,8,3><<<dim3(DI/128, MTOK/128), 256>>>(dbc, DTR+2*DS, dtw, dtbi, nullptr, dtb, MTOK, DI, DTR);
        // scan + D skip + silu(z) gating
        k_scan<<<dim3(DI/128, BQ), 128>>>(dtb, xi, dbc, xz, al, dp, y);
        // x = x + y @ out_w^T  (N=512, K=1024), residual in epilogue (in-place safe)
        k_gemm<128,128,8,8,8,2><<<dim3(DM/128, MTOK/128), 256>>>(y, DI, ow, nullptr, x, x, MTOK, DM, DI);
    }

    // 4. final layernorm -> output
    k_ln<<<MTOK, 256>>>(x, lnf_w, lnf_b, (float*)d_out);
}